// round 10
// baseline (speedup 1.0000x reference)
#include <cuda_runtime.h>

#define NTPTS 144
#define NSER_START 15      // packed series for j=0..3 seeds
#define NSER_SMALL 8       // scalar series while x2 < XTH
#define XTH 0.5f
#define TINY 1e-35f
#define L2E 1.4426950408889634f
#define TRC 0.0147f
#define T0C 1.8f
typedef unsigned long long u64;

static __device__ __forceinline__ float mlg2(float x){ float r; asm("lg2.approx.f32 %0, %1;":"=f"(r):"f"(x)); return r; }
static __device__ __forceinline__ float mex2(float x){ float r; asm("ex2.approx.f32 %0, %1;":"=f"(r):"f"(x)); return r; }
static __device__ __forceinline__ u64 pk2(float lo, float hi){ u64 r; asm("mov.b64 %0, {%1,%2};":"=l"(r):"f"(lo),"f"(hi)); return r; }
static __device__ __forceinline__ void upk2(float& lo, float& hi, u64 v){ asm("mov.b64 {%0,%1}, %2;":"=f"(lo),"=f"(hi):"l"(v)); }
static __device__ __forceinline__ u64 ffma2(u64 a, u64 b, u64 c){ u64 d; asm("fma.rn.f32x2 %0, %1, %2, %3;":"=l"(d):"l"(a),"l"(b),"l"(c)); return d; }

// Packed startup eval: P(a,x1), P(a,x2) via confluent series (K folded in c0).
static __device__ __forceinline__ void evalPP(float x1, float x2, const u64* __restrict__ rp,
                                              float a, float c0, float& P1, float& P2)
{
    float x2c = fmaxf(x2, TINY);               // a>=1 -> prefactor underflows to 0
    u64 xp = pk2(x1, x2c);
    u64 S = rp[NSER_START];
#pragma unroll
    for (int n = NSER_START - 1; n >= 0; n--) S = ffma2(S, xp, rp[n]);
    float S1, S2; upk2(S1, S2, S);
    float y1 = fmaf(a, mlg2(x1),  fmaf(-L2E, x1,  c0));
    float y2 = fmaf(a, mlg2(x2c), fmaf(-L2E, x2c, c0));
    P1 = mex2(y1) * S1;
    P2 = mex2(y2) * S2;
}

// Thread-per-row. P1,P2 advanced by 4th-order panel quadrature:
//   P_j = P_{j-1} + [ -f(j-2) + 13 f(j-1) + 13 f(j) - f(j+1) ]   (h/24 in cf)
// with f(x) = exp2((a-1)*lg2 x - L2E*x + cf) = K x^{a-1} e^{-x} step/(24 Gamma(a)).
// P2 uses the short series while x2 < XTH (x^{a-1} singularity region), stepping after.
__global__ void __launch_bounds__(128)
dynangio_kernel(const float4* __restrict__ xv4,
                const float* __restrict__ abuf,
                const float* __restrict__ rbuf,
                float* __restrict__ out, int nrows)
{
    __shared__ __align__(16) float sh_re[NTPTS];
    int tid = threadIdx.x;
    for (int i = tid; i < NTPTS; i += 128)
        sh_re[i] = rbuf[i] * sinf(abuf[i] * 0.017453292519943295f);
    __syncthreads();

    int row = blockIdx.x * 128 + tid;
    if (row >= nrows) return;

    float4 xv = xv4[row];
    float dt  = xv.x;
    float s   = xv.y;
    float pp  = xv.z;
    float amp = xv.w;

    const float INV_T1B = 0.60606060606060606f;    // 1/1.65

    float a      = fmaf(pp, s, 1.0f);              // a in [1,2)
    float b      = a - 1.0f;
    float sprime = s + INV_T1B;
    float step   = sprime * TRC;
    float W      = sprime * 1.8f;
    float x10    = sprime * (T0C - dt);            // x1 at j=0 (>= 0.48)
    // c0 = lg2( K / Gamma(a+1) ),  K = amp * 2 * exp(-dt/T1B) * (s/s')^a
    float c0 = 1.0f - dt * INV_T1B * L2E
             + a * (mlg2(s) - mlg2(sprime))
             + mlg2(amp)
             - lgammaf(a + 1.0f) * L2E;
    // cf = lg2( K * step / (24 * Gamma(a)) ) = c0 + lg2(a * step / 24)
    float cf = c0 + mlg2(a * step * (1.0f / 24.0f));

    // rho[n] = 1/prod_{k=1..n}(a+k): packed (startup) + scalar (small series)
    u64   rp[NSER_START + 1];
    float rs[NSER_SMALL + 1];
    rp[0] = pk2(1.0f, 1.0f); rs[0] = 1.0f;
    {
        float r = 1.0f, an = a;
#pragma unroll
        for (int n = 1; n <= NSER_START; n++) {
            an += 1.0f; r = __fdividef(r, an);
            rp[n] = pk2(r, r);
            if (n <= NSER_SMALL) rs[n] = r;
        }
    }

    float* outp = out + (size_t)row * NTPTS;
    const float4* re4 = (const float4*)sh_re;

    // ---- startup: j = 0..3 by direct series; seed P1 at j=3 ----
    float P1;
    {
        float4 r0; float4 re = re4[0];
        float P1j, P2j;
        evalPP(x10,                   x10 - W,                   rp, a, c0, P1j, P2j); r0.x = re.x * (P1j - P2j);
        evalPP(fmaf(1.0f, step, x10), fmaf(1.0f, step, x10) - W, rp, a, c0, P1j, P2j); r0.y = re.y * (P1j - P2j);
        evalPP(fmaf(2.0f, step, x10), fmaf(2.0f, step, x10) - W, rp, a, c0, P1j, P2j); r0.z = re.z * (P1j - P2j);
        evalPP(fmaf(3.0f, step, x10), fmaf(3.0f, step, x10) - W, rp, a, c0, P1j, P2j); r0.w = re.w * (P1j - P2j);
        ((float4*)outp)[0] = r0;
        P1 = P1j;
    }

    // ---- prime chain-1 ring: f1 at j = 2, 3, 4 ----
    float fm2_1, fm1_1, fc_1;
    {
        float x2_ = fmaf(2.0f, step, x10);
        float x3_ = fmaf(3.0f, step, x10);
        float x4_ = fmaf(4.0f, step, x10);
        fm2_1 = mex2(fmaf(b, mlg2(x2_), fmaf(-L2E, x2_, cf)));
        fm1_1 = mex2(fmaf(b, mlg2(x3_), fmaf(-L2E, x3_, cf)));
        fc_1  = mex2(fmaf(b, mlg2(x4_), fmaf(-L2E, x4_, cf)));
    }
    // chain-2 ring primes itself in-loop before it is ever selected
    float fm2_2 = 0.0f, fm1_2 = 0.0f, fc_2 = 0.0f;
    float P2acc = 0.0f;

    // ---- main loop: j = 4..143 in 35 chunks of 4 ----
#pragma unroll 1
    for (int c = 0; c < 35; c++) {
        int jb = 4 + c * 4;
        float xj = fmaf((float)jb, step, x10);     // x1 at current j (fresh base)
        float4 re = re4[c + 1];
        float rev[4] = {re.x, re.y, re.z, re.w};
        float rrv[4];

        bool need_ser = __any_sync(0xffffffffu, (xj - W) < XTH);

#pragma unroll
        for (int u = 0; u < 4; u++) {
            float xn = xj + step;                  // x1 at j+1
            // chain 1 (always stepped; x1 >= 0.48 smooth)
            float fn1 = mex2(fmaf(b, mlg2(xn), fmaf(-L2E, xn, cf)));
            P1 += fmaf(13.0f, fm1_1 + fc_1, -(fm2_1 + fn1));
            fm2_1 = fm1_1; fm1_1 = fc_1; fc_1 = fn1;

            // chain 2 stepped (f := 0 for x2 <= 0; NaN from lg2(neg) selected away)
            float x2n = xn - W;
            float f2v = mex2(fmaf(b, mlg2(x2n), fmaf(-L2E, x2n, cf)));
            float fn2 = (x2n > 0.0f) ? f2v : 0.0f;
            P2acc += fmaf(13.0f, fm1_2 + fc_2, -(fm2_2 + fn2));
            fm2_2 = fm1_2; fm1_2 = fc_2; fc_2 = fn2;

            float x2j = xj - W;
            float P2 = P2acc;
            if (need_ser) {                         // warp-uniform branch
                float x2c = fmaxf(x2j, TINY);
                float S = rs[NSER_SMALL];
#pragma unroll
                for (int n = NSER_SMALL - 1; n >= 0; n--) S = fmaf(S, x2c, rs[n]);
                float Ps = mex2(fmaf(a, mlg2(x2c), fmaf(-L2E, x2c, c0))) * S;
                P2 = (x2j < XTH) ? Ps : P2acc;
                P2acc = P2;                         // reseed: stepped takes over smoothly
            }

            rrv[u] = rev[u] * (P1 - P2);
            xj = xn;
        }
        float4 rr; rr.x = rrv[0]; rr.y = rrv[1]; rr.z = rrv[2]; rr.w = rrv[3];
        ((float4*)outp)[c + 1] = rr;
    }
}

extern "C" void kernel_launch(void* const* d_in, const int* in_sizes, int n_in,
                              void* d_out, int out_size) {
    const float4* x  = (const float4*)d_in[0];   // (B,4) float32
    const float*  al = (const float*)d_in[2];    // (144,)
    const float*  R  = (const float*)d_in[3];    // (144,)
    float* out = (float*)d_out;                  // (B,144) float32
    int nrows  = in_sizes[0] / 4;
    int blocks = (nrows + 127) / 128;            // thread-per-row
    dynangio_kernel<<<blocks, 128>>>(x, al, R, out, nrows);
}

// round 11
// speedup vs baseline: 1.1295x; 1.1295x over previous
#include <cuda_runtime.h>

#define NTPTS 144
#define NSER_START 15      // packed series for j=0..3 seeds
#define NSER_SMALL 8       // scalar series while x2 < XTH
#define XTH 0.5f
#define TINY 1e-35f
#define L2E 1.4426950408889634f
#define TRC 0.0147f
#define T0C 1.8f
typedef unsigned long long u64;

static __device__ __forceinline__ float mlg2(float x){ float r; asm("lg2.approx.f32 %0, %1;":"=f"(r):"f"(x)); return r; }
static __device__ __forceinline__ float mex2(float x){ float r; asm("ex2.approx.f32 %0, %1;":"=f"(r):"f"(x)); return r; }
static __device__ __forceinline__ u64 pk2(float lo, float hi){ u64 r; asm("mov.b64 %0, {%1,%2};":"=l"(r):"f"(lo),"f"(hi)); return r; }
static __device__ __forceinline__ void upk2(float& lo, float& hi, u64 v){ asm("mov.b64 {%0,%1}, %2;":"=f"(lo),"=f"(hi):"l"(v)); }
static __device__ __forceinline__ u64 ffma2(u64 a, u64 b, u64 c){ u64 d; asm("fma.rn.f32x2 %0, %1, %2, %3;":"=l"(d):"l"(a),"l"(b),"l"(c)); return d; }

// Packed startup eval: P(a,x1), P(a,x2) via confluent series (K folded in c0).
static __device__ __forceinline__ void evalPP(float x1, float x2, const u64* __restrict__ rp,
                                              float a, float c0, float& P1, float& P2)
{
    float x2c = fmaxf(x2, TINY);
    u64 xp = pk2(x1, x2c);
    u64 S = rp[NSER_START];
#pragma unroll
    for (int n = NSER_START - 1; n >= 0; n--) S = ffma2(S, xp, rp[n]);
    float S1, S2; upk2(S1, S2, S);
    float y1 = fmaf(a, mlg2(x1),  fmaf(-L2E, x1,  c0));
    float y2 = fmaf(a, mlg2(x2c), fmaf(-L2E, x2c, c0));
    P1 = mex2(y1) * S1;
    P2 = mex2(y2) * S2;
}

// Thread-per-row, 4th-order panel quadrature:
//   P_j = P_{j-1} + [ -f(j-2) + 13 f(j-1) + 13 f(j) - f(j+1) ]   (h/24 in cf)
//   f(x) = exp2((a-1)*lg2 x - L2E*x + cf)
// Restructured for ILP: all 8 integrand evals of a 4-point chunk are computed
// up front (independent MUFU chains), increments are independent, only the
// final running sums are serial.
__global__ void __launch_bounds__(128)
dynangio_kernel(const float4* __restrict__ xv4,
                const float* __restrict__ abuf,
                const float* __restrict__ rbuf,
                float* __restrict__ out, int nrows)
{
    __shared__ __align__(16) float sh_re[NTPTS];
    int tid = threadIdx.x;
    for (int i = tid; i < NTPTS; i += 128)
        sh_re[i] = rbuf[i] * sinf(abuf[i] * 0.017453292519943295f);
    __syncthreads();

    int row = blockIdx.x * 128 + tid;
    if (row >= nrows) return;

    float4 xv = xv4[row];
    float dt  = xv.x;
    float s   = xv.y;
    float pp  = xv.z;
    float amp = xv.w;

    const float INV_T1B = 0.60606060606060606f;    // 1/1.65

    float a      = fmaf(pp, s, 1.0f);              // a in [1,2)
    float b      = a - 1.0f;
    float sprime = s + INV_T1B;
    float step   = sprime * TRC;
    float W      = sprime * 1.8f;
    float x10    = sprime * (T0C - dt);            // x1 at j=0 (>= 0.48)
    float c0 = 1.0f - dt * INV_T1B * L2E
             + a * (mlg2(s) - mlg2(sprime))
             + mlg2(amp)
             - lgammaf(a + 1.0f) * L2E;
    float cf = c0 + mlg2(a * step * (1.0f / 24.0f));

    u64   rp[NSER_START + 1];
    float rs[NSER_SMALL + 1];
    rp[0] = pk2(1.0f, 1.0f); rs[0] = 1.0f;
    {
        float r = 1.0f, an = a;
#pragma unroll
        for (int n = 1; n <= NSER_START; n++) {
            an += 1.0f; r = __fdividef(r, an);
            rp[n] = pk2(r, r);
            if (n <= NSER_SMALL) rs[n] = r;
        }
    }

    float* outp = out + (size_t)row * NTPTS;
    const float4* re4 = (const float4*)sh_re;

    // ---- startup: j = 0..3 by direct series; seed P1 at j=3 ----
    float P1;
    {
        float4 r0; float4 re = re4[0];
        float P1j, P2j;
        evalPP(x10,                   x10 - W,                   rp, a, c0, P1j, P2j); r0.x = re.x * (P1j - P2j);
        evalPP(fmaf(1.0f, step, x10), fmaf(1.0f, step, x10) - W, rp, a, c0, P1j, P2j); r0.y = re.y * (P1j - P2j);
        evalPP(fmaf(2.0f, step, x10), fmaf(2.0f, step, x10) - W, rp, a, c0, P1j, P2j); r0.z = re.z * (P1j - P2j);
        evalPP(fmaf(3.0f, step, x10), fmaf(3.0f, step, x10) - W, rp, a, c0, P1j, P2j); r0.w = re.w * (P1j - P2j);
        ((float4*)outp)[0] = r0;
        P1 = P1j;
    }

    // ---- prime chain-1 ring: f1 at j = 2, 3, 4 ----
    float fm2_1, fm1_1, fc_1;
    {
        float x2_ = fmaf(2.0f, step, x10);
        float x3_ = fmaf(3.0f, step, x10);
        float x4_ = fmaf(4.0f, step, x10);
        fm2_1 = mex2(fmaf(b, mlg2(x2_), fmaf(-L2E, x2_, cf)));
        fm1_1 = mex2(fmaf(b, mlg2(x3_), fmaf(-L2E, x3_, cf)));
        fc_1  = mex2(fmaf(b, mlg2(x4_), fmaf(-L2E, x4_, cf)));
    }
    float fm2_2 = 0.0f, fm1_2 = 0.0f, fc_2 = 0.0f;
    float P2acc = 0.0f;

    // ---- main loop: j = 4..143 in 35 chunks of 4 ----
#pragma unroll 2
    for (int c = 0; c < 35; c++) {
        int jb = 4 + c * 4;
        float4 re = re4[c + 1];
        float rev[4] = {re.x, re.y, re.z, re.w};

        // output-point args (fresh bases: no rounding accumulation)
        float xo[4], x2o[4], xn1[4], x2n[4];
#pragma unroll
        for (int u = 0; u < 4; u++) {
            xo[u]  = fmaf((float)(jb + u), step, x10);
            x2o[u] = xo[u] - W;
            xn1[u] = xo[u] + step;          // f-eval arg: j+1
            x2n[u] = xn1[u] - W;
        }

        // batched integrand evals (8 independent MUFU chains)
        float fn1[4], fn2[4];
#pragma unroll
        for (int u = 0; u < 4; u++)
            fn1[u] = mex2(fmaf(b, mlg2(xn1[u]), fmaf(-L2E, xn1[u], cf)));
#pragma unroll
        for (int u = 0; u < 4; u++) {
            float f = mex2(fmaf(b, mlg2(x2n[u]), fmaf(-L2E, x2n[u], cf)));
            fn2[u] = (x2n[u] > 0.0f) ? f : 0.0f;   // NaN from lg2(neg) selected away
        }

        // independent panel increments (ring shifts are compile-time renames)
        float d1[4], d2[4];
        d1[0] = fmaf(13.0f, fm1_1 + fc_1,    -(fm2_1 + fn1[0]));
        d1[1] = fmaf(13.0f, fc_1 + fn1[0],   -(fm1_1 + fn1[1]));
        d1[2] = fmaf(13.0f, fn1[0] + fn1[1], -(fc_1  + fn1[2]));
        d1[3] = fmaf(13.0f, fn1[1] + fn1[2], -(fn1[0] + fn1[3]));
        d2[0] = fmaf(13.0f, fm1_2 + fc_2,    -(fm2_2 + fn2[0]));
        d2[1] = fmaf(13.0f, fc_2 + fn2[0],   -(fm1_2 + fn2[1]));
        d2[2] = fmaf(13.0f, fn2[0] + fn2[1], -(fc_2  + fn2[2]));
        d2[3] = fmaf(13.0f, fn2[1] + fn2[2], -(fn2[0] + fn2[3]));
        fm2_1 = fn1[1]; fm1_1 = fn1[2]; fc_1 = fn1[3];
        fm2_2 = fn2[1]; fm1_2 = fn2[2]; fc_2 = fn2[3];

        // running sums (short serial tails)
        float P1v[4];
        P1v[0] = P1 + d1[0];
        P1v[1] = P1v[0] + d1[1];
        P1v[2] = P1v[1] + d1[2];
        P1v[3] = P1v[2] + d1[3];
        P1 = P1v[3];

        float P2v[4];
        bool need_ser = __any_sync(0xffffffffu, x2o[0] < XTH);
        if (need_ser) {
            // batched series values (independent per u), then serial select/reseed
            float Ps[4];
#pragma unroll
            for (int u = 0; u < 4; u++) {
                float x2c = fmaxf(x2o[u], TINY);
                float S = rs[NSER_SMALL];
#pragma unroll
                for (int n = NSER_SMALL - 1; n >= 0; n--) S = fmaf(S, x2c, rs[n]);
                Ps[u] = mex2(fmaf(a, mlg2(x2c), fmaf(-L2E, x2c, c0))) * S;
            }
            float P2c = P2acc;
#pragma unroll
            for (int u = 0; u < 4; u++) {
                P2c += d2[u];
                P2c = (x2o[u] < XTH) ? Ps[u] : P2c;
                P2v[u] = P2c;
            }
            P2acc = P2c;
        } else {
            P2v[0] = P2acc + d2[0];
            P2v[1] = P2v[0] + d2[1];
            P2v[2] = P2v[1] + d2[2];
            P2v[3] = P2v[2] + d2[3];
            P2acc = P2v[3];
        }

        float4 rr;
        rr.x = rev[0] * (P1v[0] - P2v[0]);
        rr.y = rev[1] * (P1v[1] - P2v[1]);
        rr.z = rev[2] * (P1v[2] - P2v[2]);
        rr.w = rev[3] * (P1v[3] - P2v[3]);
        ((float4*)outp)[c + 1] = rr;
    }
}

extern "C" void kernel_launch(void* const* d_in, const int* in_sizes, int n_in,
                              void* d_out, int out_size) {
    const float4* x  = (const float4*)d_in[0];   // (B,4) float32
    const float*  al = (const float*)d_in[2];    // (144,)
    const float*  R  = (const float*)d_in[3];    // (144,)
    float* out = (float*)d_out;                  // (B,144) float32
    int nrows  = in_sizes[0] / 4;
    int blocks = (nrows + 127) / 128;            // thread-per-row
    dynangio_kernel<<<blocks, 128>>>(x, al, R, out, nrows);
}

// round 12
// speedup vs baseline: 2.0155x; 1.7845x over previous
#include <cuda_runtime.h>

#define NTPTS 144
#define NSER  14           // series for P2 (x2 <= 3.4) and startup P1 (x1 <= 3.0)
#define L2E 1.4426950408889634f
#define TRC 0.0147f
#define T0C 1.8f

static __device__ __forceinline__ float mlg2(float x){ float r; asm("lg2.approx.f32 %0, %1;":"=f"(r):"f"(x)); return r; }
static __device__ __forceinline__ float mex2(float x){ float r; asm("ex2.approx.f32 %0, %1;":"=f"(r):"f"(x)); return r; }

// P(a,x) * K  by confluent series (K folded into c0); x <= ~3.4 required.
// Returns 0 for x <= 0 (lg2(neg) -> NaN, selected away).
static __device__ __forceinline__ float serP(float x, const float* __restrict__ rho,
                                             float a, float c0)
{
    float S = rho[NSER];
#pragma unroll
    for (int n = NSER - 1; n >= 0; n--) S = fmaf(S, x, rho[n]);
    float y = fmaf(a, mlg2(x), fmaf(-L2E, x, c0));
    float P = mex2(y) * S;
    return (x > 0.0f) ? P : 0.0f;
}

// Integrand sample for the P1 stepping rule: f(x) = exp2(b*lg2 x - L2E*x + cf)
static __device__ __forceinline__ float feval(float x, float b, float cf)
{
    return mex2(fmaf(b, mlg2(x), fmaf(-L2E, x, cf)));
}

// Thread-per-row hybrid:
//   P1 (smooth, x1 in [0.48, 6.3]): 4th-order panel quadrature
//     P_j = P_{j-1} + [ -f(j-2) + 13 f(j-1) + 13 f(j) - f(j+1) ]  (h/24 in cf)
//   P2 (x2 always <= 3.4): direct N=14 series, no region logic, no branches.
__global__ void __launch_bounds__(128)
dynangio_kernel(const float4* __restrict__ xv4,
                const float* __restrict__ abuf,
                const float* __restrict__ rbuf,
                float* __restrict__ out, int nrows)
{
    __shared__ __align__(16) float sh_re[NTPTS];
    int tid = threadIdx.x;
    for (int i = tid; i < NTPTS; i += 128)
        sh_re[i] = rbuf[i] * sinf(abuf[i] * 0.017453292519943295f);
    __syncthreads();

    int row = blockIdx.x * 128 + tid;
    if (row >= nrows) return;

    float4 xv = xv4[row];
    float dt  = xv.x;
    float s   = xv.y;
    float pp  = xv.z;
    float amp = xv.w;

    const float INV_T1B = 0.60606060606060606f;    // 1/1.65

    float a      = fmaf(pp, s, 1.0f);              // a in [1,2)
    float b      = a - 1.0f;
    float sprime = s + INV_T1B;
    float step   = sprime * TRC;
    float W      = sprime * 1.8f;
    float x10    = sprime * (T0C - dt);            // x1 at j=0 (>= 0.48)
    // c0 = lg2( K / Gamma(a+1) ),  K = amp * 2 * exp(-dt/T1B) * (s/s')^a
    float c0 = 1.0f - dt * INV_T1B * L2E
             + a * (mlg2(s) - mlg2(sprime))
             + mlg2(amp)
             - lgammaf(a + 1.0f) * L2E;
    // cf = c0 + lg2(a * step / 24)   (prefactor for the integrand samples)
    float cf = c0 + mlg2(a * step * (1.0f / 24.0f));

    // rho[n] = 1/prod_{k=1..n}(a+k)  (scalar, registers)
    float rho[NSER + 1];
    rho[0] = 1.0f;
    {
        float r = 1.0f, an = a;
#pragma unroll
        for (int n = 1; n <= NSER; n++) { an += 1.0f; r = __fdividef(r, an); rho[n] = r; }
    }

    float* outp = out + (size_t)row * NTPTS;
    const float4* re4 = (const float4*)sh_re;

    // ---- startup: j = 0..3 by direct series (x1 <= ~3.0 here); seed P1 at j=3 ----
    float P1;
    {
        float x0 = x10;
        float x1_ = fmaf(1.0f, step, x10);
        float x2_ = fmaf(2.0f, step, x10);
        float x3_ = fmaf(3.0f, step, x10);
        float p0 = serP(x0, rho, a, c0), q0 = serP(x0 - W, rho, a, c0);
        float p1 = serP(x1_, rho, a, c0), q1 = serP(x1_ - W, rho, a, c0);
        float p2 = serP(x2_, rho, a, c0), q2 = serP(x2_ - W, rho, a, c0);
        float p3 = serP(x3_, rho, a, c0), q3 = serP(x3_ - W, rho, a, c0);
        float4 re = re4[0];
        float4 r0;
        r0.x = re.x * (p0 - q0);
        r0.y = re.y * (p1 - q1);
        r0.z = re.z * (p2 - q2);
        r0.w = re.w * (p3 - q3);
        ((float4*)outp)[0] = r0;
        P1 = p3;
    }

    // ---- prime P1 ring: f at j = 2, 3, 4 ----
    float fm2 = feval(fmaf(2.0f, step, x10), b, cf);
    float fm1 = feval(fmaf(3.0f, step, x10), b, cf);
    float fc  = feval(fmaf(4.0f, step, x10), b, cf);

    // ---- main loop: j = 4..143 in 35 chunks of 4 ----
#pragma unroll 2
    for (int c = 0; c < 35; c++) {
        int jb = 4 + c * 4;
        float4 re = re4[c + 1];

        // args (fresh bases: no rounding accumulation)
        float xo[4], x2o[4];
#pragma unroll
        for (int u = 0; u < 4; u++) {
            xo[u]  = fmaf((float)(jb + u), step, x10);
            x2o[u] = xo[u] - W;
        }

        // P1 integrand samples at j+1 (4 independent MUFU chains)
        float fn[4];
#pragma unroll
        for (int u = 0; u < 4; u++)
            fn[u] = feval(xo[u] + step, b, cf);

        // independent panel increments (ring shifts are compile-time renames)
        float d1[4];
        d1[0] = fmaf(13.0f, fm1 + fc,     -(fm2 + fn[0]));
        d1[1] = fmaf(13.0f, fc + fn[0],   -(fm1 + fn[1]));
        d1[2] = fmaf(13.0f, fn[0] + fn[1], -(fc  + fn[2]));
        d1[3] = fmaf(13.0f, fn[1] + fn[2], -(fn[0] + fn[3]));
        fm2 = fn[1]; fm1 = fn[2]; fc = fn[3];

        // serial prefix (short)
        float P1v[4];
        P1v[0] = P1 + d1[0];
        P1v[1] = P1v[0] + d1[1];
        P1v[2] = P1v[1] + d1[2];
        P1v[3] = P1v[2] + d1[3];
        P1 = P1v[3];

        // P2 by direct series — always valid (x2 <= 3.4), 4 independent Horners
        float P2v[4];
#pragma unroll
        for (int u = 0; u < 4; u++)
            P2v[u] = serP(x2o[u], rho, a, c0);

        float4 rr;
        rr.x = re.x * (P1v[0] - P2v[0]);
        rr.y = re.y * (P1v[1] - P2v[1]);
        rr.z = re.z * (P1v[2] - P2v[2]);
        rr.w = re.w * (P1v[3] - P2v[3]);
        ((float4*)outp)[c + 1] = rr;
    }
}

extern "C" void kernel_launch(void* const* d_in, const int* in_sizes, int n_in,
                              void* d_out, int out_size) {
    const float4* x  = (const float4*)d_in[0];   // (B,4) float32
    const float*  al = (const float*)d_in[2];    // (144,)
    const float*  R  = (const float*)d_in[3];    // (144,)
    float* out = (float*)d_out;                  // (B,144) float32
    int nrows  = in_sizes[0] / 4;
    int blocks = (nrows + 127) / 128;            // thread-per-row
    dynangio_kernel<<<blocks, 128>>>(x, al, R, out, nrows);
}

// round 13
// speedup vs baseline: 2.2180x; 1.1005x over previous
#include <cuda_runtime.h>

#define NTPTS 144
#define NSER  13           // series for P2 (x2 <= 3.4) and startup (x <= 3.0)
#define L2E 1.4426950408889634f
#define TRC 0.0147f
#define T0C 1.8f
typedef unsigned long long u64;

static __device__ __forceinline__ float mlg2(float x){ float r; asm("lg2.approx.f32 %0, %1;":"=f"(r):"f"(x)); return r; }
static __device__ __forceinline__ float mex2(float x){ float r; asm("ex2.approx.f32 %0, %1;":"=f"(r):"f"(x)); return r; }
static __device__ __forceinline__ u64 pk2(float lo, float hi){ u64 r; asm("mov.b64 %0, {%1,%2};":"=l"(r):"f"(lo),"f"(hi)); return r; }
static __device__ __forceinline__ void upk2(float& lo, float& hi, u64 v){ asm("mov.b64 {%0,%1}, %2;":"=f"(lo),"=f"(hi):"l"(v)); }
static __device__ __forceinline__ u64 ffma2(u64 a, u64 b, u64 c){ u64 d; asm("fma.rn.f32x2 %0, %1, %2, %3;":"=l"(d):"l"(a),"l"(b),"l"(c)); return d; }

// Integrand sample for the P1 stepping rule: f(x) = exp2(b*lg2 x - L2E*x + cf)
static __device__ __forceinline__ float feval(float x, float b, float cf)
{
    return mex2(fmaf(b, mlg2(x), fmaf(-L2E, x, cf)));
}

// Packed-pair series: PA = K*P(a,xA), PB = K*P(a,xB), one packed Horner
// (rho duplicated), scalar prefactors. x<=0 -> 0 (lg2(neg)->NaN selected away).
static __device__ __forceinline__ void serP2(float xA, float xB,
                                             const u64* __restrict__ rp,
                                             float a, float c0,
                                             float& PA, float& PB)
{
    u64 xp = pk2(xA, xB);
    u64 S = rp[NSER];
#pragma unroll
    for (int n = NSER - 1; n >= 0; n--) S = ffma2(S, xp, rp[n]);
    float SA, SB; upk2(SA, SB, S);
    float yA = fmaf(a, mlg2(xA), fmaf(-L2E, xA, c0));
    float yB = fmaf(a, mlg2(xB), fmaf(-L2E, xB, c0));
    float pA = mex2(yA) * SA;
    float pB = mex2(yB) * SB;
    PA = (xA > 0.0f) ? pA : 0.0f;
    PB = (xB > 0.0f) ? pB : 0.0f;
}

// Thread-per-row hybrid:
//   P1 (smooth, x1 in [0.48, 6.3]): 4th-order panel quadrature
//     P_j = P_{j-1} + [ -f(j-2) + 13 f(j-1) + 13 f(j) - f(j+1) ]  (h/24 in cf)
//   P2 (x2 always <= 3.4): direct series, packed in point-pairs.
__global__ void __launch_bounds__(128)
dynangio_kernel(const float4* __restrict__ xv4,
                const float* __restrict__ abuf,
                const float* __restrict__ rbuf,
                float* __restrict__ out, int nrows)
{
    __shared__ __align__(16) float sh_re[NTPTS];
    int tid = threadIdx.x;
    for (int i = tid; i < NTPTS; i += 128)
        sh_re[i] = rbuf[i] * sinf(abuf[i] * 0.017453292519943295f);
    __syncthreads();

    int row = blockIdx.x * 128 + tid;
    if (row >= nrows) return;

    float4 xv = xv4[row];
    float dt  = xv.x;
    float s   = xv.y;
    float pp  = xv.z;
    float amp = xv.w;

    const float INV_T1B = 0.60606060606060606f;    // 1/1.65

    float a      = fmaf(pp, s, 1.0f);              // a in [1,2)
    float b      = a - 1.0f;
    float sprime = s + INV_T1B;
    float step   = sprime * TRC;
    float W      = sprime * 1.8f;
    float x10    = sprime * (T0C - dt);            // x1 at j=0 (>= 0.48)
    // c0 = lg2( K / Gamma(a+1) ),  K = amp * 2 * exp(-dt/T1B) * (s/s')^a
    float c0 = 1.0f - dt * INV_T1B * L2E
             + a * (mlg2(s) - mlg2(sprime))
             + mlg2(amp)
             - lgammaf(a + 1.0f) * L2E;
    // cf = c0 + lg2(a * step / 24)   (integrand-sample prefactor)
    float cf = c0 + mlg2(a * step * (1.0f / 24.0f));

    // rho[n] = 1/prod_{k=1..n}(a+k), duplicated into packed pairs
    u64 rp[NSER + 1];
    rp[0] = pk2(1.0f, 1.0f);
    {
        float r = 1.0f, an = a;
#pragma unroll
        for (int n = 1; n <= NSER; n++) { an += 1.0f; r = __fdividef(r, an); rp[n] = pk2(r, r); }
    }

    float st2 = step + step;
    float st3 = st2 + step;
    float st4 = st2 + st2;

    float* outp = out + (size_t)row * NTPTS;
    const float4* re4 = (const float4*)sh_re;

    // ---- startup: j = 0..3 by direct series (x1 <= ~3.0 here); seed P1 at j=3 ----
    float P1;
    {
        float xa0 = x10,        xa1 = x10 + step;
        float xa2 = x10 + st2,  xa3 = x10 + st3;
        float p0, q0, p1, q1, p2, q2, p3, q3;
        serP2(xa0, xa0 - W, rp, a, c0, p0, q0);
        serP2(xa1, xa1 - W, rp, a, c0, p1, q1);
        serP2(xa2, xa2 - W, rp, a, c0, p2, q2);
        serP2(xa3, xa3 - W, rp, a, c0, p3, q3);
        float4 re = re4[0];
        float4 r0;
        r0.x = re.x * (p0 - q0);
        r0.y = re.y * (p1 - q1);
        r0.z = re.z * (p2 - q2);
        r0.w = re.w * (p3 - q3);
        ((float4*)outp)[0] = r0;
        P1 = p3;
    }

    // ---- prime P1 ring: f at j = 2, 3, 4 ----
    float fm2 = feval(x10 + st2, b, cf);
    float fm1 = feval(x10 + st3, b, cf);
    float fc  = feval(x10 + st4, b, cf);

    float jf = 4.0f;                               // chunk base index (exact)

    // ---- main loop: j = 4..143 in 35 chunks of 4 ----
#pragma unroll 2
    for (int c = 0; c < 35; c++) {
        float4 re = re4[c + 1];

        // chunk points (fresh fma base per chunk; jf integer-exact)
        float xo0 = fmaf(jf, step, x10);
        float xo1 = xo0 + step;
        float xo2 = xo0 + st2;
        float xo3 = xo0 + st3;
        float xo4 = xo0 + st4;                     // f-arg for u=3
        jf += 4.0f;

        // P1 integrand samples at j+1 (args are simply the next points)
        float fn0 = feval(xo1, b, cf);
        float fn1 = feval(xo2, b, cf);
        float fn2 = feval(xo3, b, cf);
        float fn3 = feval(xo4, b, cf);

        // independent panel increments
        float d10 = fmaf(13.0f, fm1 + fc,  -(fm2 + fn0));
        float d11 = fmaf(13.0f, fc + fn0,  -(fm1 + fn1));
        float d12 = fmaf(13.0f, fn0 + fn1, -(fc  + fn2));
        float d13 = fmaf(13.0f, fn1 + fn2, -(fn0 + fn3));
        fm2 = fn1; fm1 = fn2; fc = fn3;

        // serial prefix (short)
        float P10 = P1 + d10;
        float P11 = P10 + d11;
        float P12 = P11 + d12;
        float P13 = P12 + d13;
        P1 = P13;

        // P2 by packed-pair series (x2 <= 3.4 always)
        float P20, P21, P22, P23;
        serP2(xo0 - W, xo1 - W, rp, a, c0, P20, P21);
        serP2(xo2 - W, xo3 - W, rp, a, c0, P22, P23);

        float4 rr;
        rr.x = re.x * (P10 - P20);
        rr.y = re.y * (P11 - P21);
        rr.z = re.z * (P12 - P22);
        rr.w = re.w * (P13 - P23);
        ((float4*)outp)[c + 1] = rr;
    }
}

extern "C" void kernel_launch(void* const* d_in, const int* in_sizes, int n_in,
                              void* d_out, int out_size) {
    const float4* x  = (const float4*)d_in[0];   // (B,4) float32
    const float*  al = (const float*)d_in[2];    // (144,)
    const float*  R  = (const float*)d_in[3];    // (144,)
    float* out = (float*)d_out;                  // (B,144) float32
    int nrows  = in_sizes[0] / 4;
    int blocks = (nrows + 127) / 128;            // thread-per-row
    dynangio_kernel<<<blocks, 128>>>(x, al, R, out, nrows);
}